// round 16
// baseline (speedup 1.0000x reference)
#include <cuda_runtime.h>
#include <cuda_bf16.h>

// Problem constants (fixed by setup_inputs)
#define B_    4
#define C_    64
#define H_    256
#define W_    512
#define D_    48
#define TW    128           // output w-tile per CTA
#define RW    (TW + 48)     // right tile width incl. 48-left halo (aligned: starts at w0-48)
#define NTHREADS 192        // 6 d-groups (of 8) x 32 w-groups (of 4)

extern __shared__ float smem[];   // [C_*TW] left + [C_*RW] right = 77824 B

__global__ void __launch_bounds__(NTHREADS, 2)
cost_volume_kernel(const float* __restrict__ left,
                   const float* __restrict__ right,
                   float* __restrict__ out)
{
    float* __restrict__ left_s  = smem;             // [C_][TW]
    float* __restrict__ right_s = smem + C_ * TW;   // [C_][RW]

    const int w0  = blockIdx.x * TW;   // 0..384
    const int h   = blockIdx.y;
    const int b   = blockIdx.z;
    const int tid = threadIdx.x;

    const size_t plane = (size_t)H_ * W_;

    // ---- stage left tile: L[b, c, h, w0 .. w0+127] ----
    {
        const float* lb = left + ((size_t)b * C_) * plane + (size_t)h * W_ + w0;
        #pragma unroll 4
        for (int i = tid; i < C_ * (TW / 4); i += NTHREADS) {
            const int c = i / (TW / 4);
            const int j = i % (TW / 4);
            const float4 v = *(const float4*)(lb + (size_t)c * plane + 4 * j);
            *(float4*)&left_s[c * TW + 4 * j] = v;
        }
    }
    // ---- stage right tile: R[b, c, h, w0-48 .. w0+127], zero-fill w<0 ----
    {
        const float* rb = right + ((size_t)b * C_) * plane + (size_t)h * W_ + (w0 - 48);
        #pragma unroll 4
        for (int i = tid; i < C_ * (RW / 4); i += NTHREADS) {
            const int c  = i / (RW / 4);
            const int j  = i % (RW / 4);
            const int gw = w0 - 48 + 4 * j;         // aligned: gw%4==0, boundary at 0
            float4 v;
            if (gw >= 0) v = *(const float4*)(rb + (size_t)c * plane + 4 * j);
            else         v = make_float4(0.f, 0.f, 0.f, 0.f);
            *(float4*)&right_s[c * RW + 4 * j] = v;
        }
    }
    __syncthreads();

    // ---- register tile: 8 disparities x 4 widths per thread ----
    const int wgl = tid & 31;        // warp = one d-group, lanes = w-groups
    const int dg  = tid >> 5;        // 0..5
    const int ww0 = wgl * 4;         // 0..124
    const int d0  = dg * 8;          // 0..40
    // right smem index for (ww, d): ww - d + 48. Needed window for this thread:
    // [ww0 - d0 + 41, ww0 - d0 + 51]; rb4 = ww0 - d0 + 40 is 4-aligned, load 12 floats.
    const int rb4 = ww0 - d0 + 40;

    float acc[8][4];
    #pragma unroll
    for (int i = 0; i < 8; i++)
        acc[i][0] = acc[i][1] = acc[i][2] = acc[i][3] = 0.f;

    #pragma unroll 4
    for (int c = 0; c < C_; c++) {
        const float4 l  = *(const float4*)&left_s[c * TW + ww0];
        const float4 r0 = *(const float4*)&right_s[c * RW + rb4];
        const float4 r1 = *(const float4*)&right_s[c * RW + rb4 + 4];
        const float4 r2 = *(const float4*)&right_s[c * RW + rb4 + 8];
        const float r[12] = { r0.x, r0.y, r0.z, r0.w,
                              r1.x, r1.y, r1.z, r1.w,
                              r2.x, r2.y, r2.z, r2.w };
        #pragma unroll
        for (int dd = 0; dd < 8; dd++) {
            const int o = 8 - dd;    // r[o + k] == right_s[c][ww0 + k - (d0+dd) + 48]
            acc[dd][0] += l.x * r[o];
            acc[dd][1] += l.y * r[o + 1];
            acc[dd][2] += l.z * r[o + 2];
            acc[dd][3] += l.w * r[o + 3];
        }
    }

    // ---- epilogue: mean over C and store (coalesced float4) ----
    const float inv = 1.0f / (float)C_;
    float* ob = out + ((size_t)b * D_) * plane + (size_t)h * W_ + w0 + ww0;
    #pragma unroll
    for (int dd = 0; dd < 8; dd++) {
        const int d = d0 + dd;
        float4 v = make_float4(acc[dd][0] * inv, acc[dd][1] * inv,
                               acc[dd][2] * inv, acc[dd][3] * inv);
        *(float4*)(ob + (size_t)d * plane) = v;
    }
}

extern "C" void kernel_launch(void* const* d_in, const int* in_sizes, int n_in,
                              void* d_out, int out_size)
{
    const float* left  = (const float*)d_in[0];
    const float* right = (const float*)d_in[1];
    float* out = (float*)d_out;

    const int smem_bytes = (C_ * TW + C_ * RW) * (int)sizeof(float);  // 77824
    cudaFuncSetAttribute(cost_volume_kernel,
                         cudaFuncAttributeMaxDynamicSharedMemorySize, smem_bytes);

    dim3 grid(W_ / TW, H_, B_);   // (4, 256, 4)
    cost_volume_kernel<<<grid, NTHREADS, smem_bytes>>>(left, right, out);
}

// round 17
// speedup vs baseline: 1.1887x; 1.1887x over previous
#include <cuda_runtime.h>
#include <cuda_bf16.h>

// Problem constants (fixed by setup_inputs)
#define B_    4
#define C_    64
#define W_    512
#define H_    256
#define D_    48
#define TW    128           // output w-tile per CTA
#define RW    (TW + 48)     // right tile width incl. 48-left halo
#define CSPLIT 32           // channels staged per phase (2 phases)
#define NTHREADS 192        // 6 d-groups (of 8) x 32 w-groups (of 4)

extern __shared__ float smem[];   // CSPLIT*(TW+RW) floats = 38912 B

__global__ void __launch_bounds__(NTHREADS, 4)
cost_volume_kernel(const float* __restrict__ left,
                   const float* __restrict__ right,
                   float* __restrict__ out)
{
    float* __restrict__ left_s  = smem;                 // [CSPLIT][TW]
    float* __restrict__ right_s = smem + CSPLIT * TW;   // [CSPLIT][RW]

    const int w0  = blockIdx.x * TW;   // 0..384
    const int h   = blockIdx.y;
    const int b   = blockIdx.z;
    const int tid = threadIdx.x;

    const size_t plane = (size_t)H_ * W_;

    // per-thread register tile coordinates
    const int wgl = tid & 31;        // lane -> w-group
    const int dg  = tid >> 5;        // warp -> d-group (0..5)
    const int ww0 = wgl * 4;         // 0..124
    const int d0  = dg * 8;          // 0..40
    // right smem window for this thread: indices ww0 - d0 + [41,51]; aligned base:
    const int rb4 = ww0 - d0 + 40;

    float acc[8][4];
    #pragma unroll
    for (int i = 0; i < 8; i++)
        acc[i][0] = acc[i][1] = acc[i][2] = acc[i][3] = 0.f;

    const float* lb = left  + ((size_t)b * C_) * plane + (size_t)h * W_ + w0;
    const float* rb = right + ((size_t)b * C_) * plane + (size_t)h * W_ + (w0 - 48);

    for (int ph = 0; ph < 2; ph++) {
        const size_t cbase = (size_t)(ph * CSPLIT) * plane;

        // ---- stage left half-tile: L[b, c0..c0+31, h, w0 .. w0+127] ----
        #pragma unroll 4
        for (int i = tid; i < CSPLIT * (TW / 4); i += NTHREADS) {
            const int c = i / (TW / 4);
            const int j = i % (TW / 4);
            const float4 v = *(const float4*)(lb + cbase + (size_t)c * plane + 4 * j);
            *(float4*)&left_s[c * TW + 4 * j] = v;
        }
        // ---- stage right half-tile: R[b, c0.., h, w0-48 .. w0+127], zero-fill w<0 ----
        #pragma unroll 4
        for (int i = tid; i < CSPLIT * (RW / 4); i += NTHREADS) {
            const int c  = i / (RW / 4);
            const int j  = i % (RW / 4);
            const int gw = w0 - 48 + 4 * j;     // 4-aligned, boundary exactly at 0
            float4 v;
            if (gw >= 0) v = *(const float4*)(rb + cbase + (size_t)c * plane + 4 * j);
            else         v = make_float4(0.f, 0.f, 0.f, 0.f);
            *(float4*)&right_s[c * RW + 4 * j] = v;
        }
        __syncthreads();

        // ---- compute over this channel half ----
        #pragma unroll 4
        for (int c = 0; c < CSPLIT; c++) {
            const float4 l  = *(const float4*)&left_s[c * TW + ww0];
            const float4 r0 = *(const float4*)&right_s[c * RW + rb4];
            const float4 r1 = *(const float4*)&right_s[c * RW + rb4 + 4];
            const float4 r2 = *(const float4*)&right_s[c * RW + rb4 + 8];
            const float r[12] = { r0.x, r0.y, r0.z, r0.w,
                                  r1.x, r1.y, r1.z, r1.w,
                                  r2.x, r2.y, r2.z, r2.w };
            #pragma unroll
            for (int dd = 0; dd < 8; dd++) {
                const int o = 8 - dd;   // r[o+k] == right_s[c][ww0+k - (d0+dd) + 48]
                acc[dd][0] += l.x * r[o];
                acc[dd][1] += l.y * r[o + 1];
                acc[dd][2] += l.z * r[o + 2];
                acc[dd][3] += l.w * r[o + 3];
            }
        }
        __syncthreads();
    }

    // ---- epilogue: mean over C and store (coalesced float4 per d-plane) ----
    const float inv = 1.0f / (float)C_;
    float* ob = out + ((size_t)b * D_) * plane + (size_t)h * W_ + w0 + ww0;
    #pragma unroll
    for (int dd = 0; dd < 8; dd++) {
        const int d = d0 + dd;
        float4 v = make_float4(acc[dd][0] * inv, acc[dd][1] * inv,
                               acc[dd][2] * inv, acc[dd][3] * inv);
        *(float4*)(ob + (size_t)d * plane) = v;
    }
}

extern "C" void kernel_launch(void* const* d_in, const int* in_sizes, int n_in,
                              void* d_out, int out_size)
{
    const float* left  = (const float*)d_in[0];
    const float* right = (const float*)d_in[1];
    float* out = (float*)d_out;

    const int smem_bytes = CSPLIT * (TW + RW) * (int)sizeof(float);  // 38912
    cudaFuncSetAttribute(cost_volume_kernel,
                         cudaFuncAttributeMaxDynamicSharedMemorySize, smem_bytes);

    dim3 grid(W_ / TW, H_, B_);   // (4, 256, 4)
    cost_volume_kernel<<<grid, NTHREADS, smem_bytes>>>(left, right, out);
}